// round 1
// baseline (speedup 1.0000x reference)
#include <cuda_runtime.h>
#include <cstdint>

// Problem constants
#define TT   500
#define BB   128
#define CC   700
#define CP   704      // padded K
#define HH   1024
#define OO   20
#define MM   (TT*BB)  // 64000

// Scratch (device globals — no runtime allocation allowed)
__device__ float g_xd[(size_t)MM * CP];        // delayed input, row m=(t*128+b), K-padded
__device__ float g_winT[(size_t)CP * HH];      // w_in transposed [c][h], zero-padded rows
__device__ float g_wrecT[(size_t)HH * HH];     // w_rec transposed [j][h]
__device__ float g_Iin[(size_t)MM * HH];       // I_in[m][h]

// ---------------------------------------------------------------------------
// Prep: transpose w_in -> [CP][HH] with zero pad
__global__ void prep_winT(const float* __restrict__ w_in) {
    int idx = blockIdx.x * blockDim.x + threadIdx.x;
    if (idx >= CP * HH) return;
    int k = idx >> 10;         // 0..703
    int h = idx & 1023;
    g_winT[idx] = (k < CC) ? w_in[h * CC + k] : 0.f;
}

// Prep: transpose w_rec -> [j][h]
__global__ void prep_wrecT(const float* __restrict__ w_rec) {
    int idx = blockIdx.x * blockDim.x + threadIdx.x;
    if (idx >= HH * HH) return;
    int j = idx >> 10;
    int h = idx & 1023;
    g_wrecT[idx] = w_rec[h * HH + j];
}

// Prep: build delayed input xd[m][c], m = t*128 + b
__global__ void build_xd(const float* __restrict__ x, const int* __restrict__ delays) {
    size_t gid = (size_t)blockIdx.x * blockDim.x + threadIdx.x;
    const size_t total = (size_t)MM * CP;
    if (gid >= total) return;
    int c = (int)(gid % CP);
    int m = (int)(gid / CP);
    float v = 0.f;
    if (c < CC) {
        int t = m >> 7;
        int b = m & 127;
        int ts = t - delays[c];
        if (ts >= 0) v = x[((size_t)b * TT + ts) * CC + c];
    }
    g_xd[gid] = v;
}

// ---------------------------------------------------------------------------
// fp32 SGEMM: C[M][HH] = g_xd[M][CP] * g_winT[CP][HH]
// 128x128 tile, BK=8, 256 threads, 8x8 per thread
__global__ __launch_bounds__(256) void sgemm128(void) {
    __shared__ float As[8][128];
    __shared__ float Bs[8][128];

    const int bx = blockIdx.x;   // N tile: 0..7
    const int by = blockIdx.y;   // M tile: 0..499
    const int tid = threadIdx.x;
    const int tx = tid & 15;     // N dir
    const int ty = tid >> 4;     // M dir

    const int rowA = tid >> 1;
    const int colA = (tid & 1) * 4;
    const int rowB = tid >> 5;
    const int colB = (tid & 31) * 4;

    const float* Ab = g_xd + (size_t)(by * 128) * CP;
    float acc[8][8];
    #pragma unroll
    for (int i = 0; i < 8; i++)
        #pragma unroll
        for (int j = 0; j < 8; j++) acc[i][j] = 0.f;

    for (int k0 = 0; k0 < CP; k0 += 8) {
        float4 a4 = *(const float4*)(Ab + (size_t)rowA * CP + k0 + colA);
        As[colA + 0][rowA] = a4.x;
        As[colA + 1][rowA] = a4.y;
        As[colA + 2][rowA] = a4.z;
        As[colA + 3][rowA] = a4.w;
        float4 b4 = *(const float4*)(g_winT + (size_t)(k0 + rowB) * HH + bx * 128 + colB);
        *(float4*)&Bs[rowB][colB] = b4;
        __syncthreads();
        #pragma unroll
        for (int k = 0; k < 8; k++) {
            float4 a0 = *(const float4*)&As[k][ty * 8];
            float4 a1 = *(const float4*)&As[k][ty * 8 + 4];
            float4 b0 = *(const float4*)&Bs[k][tx * 8];
            float4 b1 = *(const float4*)&Bs[k][tx * 8 + 4];
            float ra[8] = {a0.x, a0.y, a0.z, a0.w, a1.x, a1.y, a1.z, a1.w};
            float rb[8] = {b0.x, b0.y, b0.z, b0.w, b1.x, b1.y, b1.z, b1.w};
            #pragma unroll
            for (int i = 0; i < 8; i++)
                #pragma unroll
                for (int j = 0; j < 8; j++)
                    acc[i][j] += ra[i] * rb[j];
        }
        __syncthreads();
    }

    #pragma unroll
    for (int i = 0; i < 8; i++) {
        float* Cr = g_Iin + (size_t)(by * 128 + ty * 8 + i) * HH + bx * 128 + tx * 8;
        float4 c0 = {acc[i][0], acc[i][1], acc[i][2], acc[i][3]};
        float4 c1 = {acc[i][4], acc[i][5], acc[i][6], acc[i][7]};
        *(float4*)(Cr)     = c0;
        *(float4*)(Cr + 4) = c1;
    }
}

// ---------------------------------------------------------------------------
// Persistent sequential SNN: one CTA per batch, 1024 threads = one per hidden unit.
// State (v, a, spk) lives in registers; spikes exchanged via smem active list.
__global__ __launch_bounds__(1024, 1) void snn_seq(
    const float* __restrict__ w_out,
    const float* __restrict__ alpha, const float* __restrict__ rho,
    const float* __restrict__ beta_a, const float* __restrict__ beta_out,
    float* __restrict__ out)
{
    const int b = blockIdx.x;
    const int h = threadIdx.x;
    const int lane = h & 31;
    const int wid = h >> 5;

    __shared__ int act[HH];
    __shared__ int warp_cnt[32];
    __shared__ int warp_off[32];
    __shared__ int n_act_s;

    float v = 0.f, a = 0.f, spk = 0.f;
    const float al = alpha[h], rh = rho[h], ba = beta_a[h];
    float v_out = 0.f, osum = 0.f;
    float bo = 0.f;
    if (h < OO) bo = beta_out[h];
    int n_act = 0;

    float Icur = g_Iin[(size_t)b * HH + h];   // t = 0 row: m = b

    for (int t = 0; t < TT; ++t) {
        // prefetch next timestep's input current
        float Inext = 0.f;
        if (t < TT - 1)
            Inext = g_Iin[((size_t)((t + 1) * BB + b)) * HH + h];

        // sparse recurrent input: sum rows of w_recT for active units (prev step)
        float Irec = 0.f;
        {
            int i = 0;
            for (; i + 4 <= n_act; i += 4) {
                int j0 = act[i], j1 = act[i + 1], j2 = act[i + 2], j3 = act[i + 3];
                Irec += g_wrecT[(size_t)j0 * HH + h];
                Irec += g_wrecT[(size_t)j1 * HH + h];
                Irec += g_wrecT[(size_t)j2 * HH + h];
                Irec += g_wrecT[(size_t)j3 * HH + h];
            }
            for (; i < n_act; ++i)
                Irec += g_wrecT[(size_t)act[i] * HH + h];
        }

        // adaptive LIF update (exact reference math, fp32)
        float I1   = Icur + Irec;
        float vn   = al * v * (1.f - spk) + (1.f - al) * (I1 - a);
        float spkn = (vn > 1.0f) ? 1.f : 0.f;
        a = rh * a + (1.f - rh) * (ba * vn + spkn);
        v = vn;
        spk = spkn;

        // deterministic active-list build (ballot + warp-count scan, index order)
        unsigned msk = __ballot_sync(0xffffffffu, spkn != 0.f);
        if (lane == 0) warp_cnt[wid] = __popc(msk);
        __syncthreads();                       // warp_cnt visible; old act reads done
        if (wid == 0) {
            int cc = warp_cnt[lane];
            int s = cc;
            #pragma unroll
            for (int d = 1; d < 32; d <<= 1) {
                int y = __shfl_up_sync(0xffffffffu, s, d);
                if (lane >= d) s += y;
            }
            warp_off[lane] = s - cc;           // exclusive prefix
            if (lane == 31) n_act_s = s;
        }
        __syncthreads();                       // offsets ready
        if (spkn != 0.f) {
            int pos = warp_off[wid] + __popc(msk & ((1u << lane) - 1u));
            act[pos] = h;
        }
        __syncthreads();                       // new act complete
        n_act = n_act_s;

        // readout: I_out = spk_n @ w_out.T (sparse over new active list)
        if (h < OO) {
            float accum = 0.f;
            for (int i = 0; i < n_act; ++i)
                accum += w_out[h * HH + act[i]];
            v_out = bo * v_out + (1.f - bo) * accum;
            osum += v_out;
        }
        Icur = Inext;
    }

    if (h < OO) out[b * OO + h] = osum * (1.f / (float)TT);
}

// ---------------------------------------------------------------------------
extern "C" void kernel_launch(void* const* d_in, const int* in_sizes, int n_in,
                              void* d_out, int out_size)
{
    const float* x        = (const float*)d_in[0];
    const int*   delays   = (const int*)  d_in[1];
    const float* w_in     = (const float*)d_in[2];
    const float* w_rec    = (const float*)d_in[3];
    const float* w_out    = (const float*)d_in[4];
    const float* alpha    = (const float*)d_in[5];
    const float* rho      = (const float*)d_in[6];
    const float* beta_a   = (const float*)d_in[7];
    const float* beta_out = (const float*)d_in[8];
    float* out = (float*)d_out;

    prep_winT <<<(CP * HH + 255) / 256, 256>>>(w_in);
    prep_wrecT<<<(HH * HH + 255) / 256, 256>>>(w_rec);
    {
        size_t total = (size_t)MM * CP;
        int blocks = (int)((total + 255) / 256);
        build_xd<<<blocks, 256>>>(x, delays);
    }
    {
        dim3 grid(HH / 128, MM / 128);   // (8, 500)
        sgemm128<<<grid, 256>>>();
    }
    snn_seq<<<BB, 1024>>>(w_out, alpha, rho, beta_a, beta_out, out);
}

// round 4
// speedup vs baseline: 1.9435x; 1.9435x over previous
#include <cuda_runtime.h>
#include <cuda_bf16.h>
#include <cstdint>

// Problem constants
#define TT   500
#define BB   128
#define CC   700
#define CP   704      // padded K
#define HH   1024
#define OO   20
#define MM   (TT*BB)  // 64000

// ---------------------------------------------------------------------------
// Device scratch (no runtime allocation allowed)
__device__ __nv_bfloat16 g_xh[(size_t)MM * CP];   // delayed input hi, row m=(t*128+b)
__device__ __nv_bfloat16 g_xl[(size_t)MM * CP];   // delayed input lo
__device__ __nv_bfloat16 g_wh[(size_t)HH * CP];   // w_in hi  [h][k], K-padded
__device__ __nv_bfloat16 g_wl[(size_t)HH * CP];   // w_in lo
__device__ float g_wrecT[(size_t)HH * HH];        // w_rec transposed [j][h]
__device__ float g_Iin[(size_t)MM * HH];          // I_in[m][h]

// ---------------------------------------------------------------------------
__device__ __forceinline__ uint32_t smem_u32(const void* p) {
    uint32_t a;
    asm("{ .reg .u64 t; cvta.to.shared.u64 t, %1; cvt.u32.u64 %0, t; }" : "=r"(a) : "l"(p));
    return a;
}
#define CP16(dst, src) asm volatile("cp.async.cg.shared.global [%0], [%1], 16;" :: "r"(dst), "l"(src) : "memory")
#define CP_COMMIT()    asm volatile("cp.async.commit_group;" ::: "memory")
#define CP_WAIT1()     asm volatile("cp.async.wait_group 1;" ::: "memory")

__device__ __forceinline__ void ldsm_x4(uint32_t* r, uint32_t addr) {
    asm volatile("ldmatrix.sync.aligned.m8n8.x4.shared.b16 {%0,%1,%2,%3}, [%4];"
        : "=r"(r[0]), "=r"(r[1]), "=r"(r[2]), "=r"(r[3]) : "r"(addr));
}
__device__ __forceinline__ void mma16816(float* d, const uint32_t* a, uint32_t b0, uint32_t b1) {
    asm volatile(
        "mma.sync.aligned.m16n8k16.row.col.f32.bf16.bf16.f32 "
        "{%0,%1,%2,%3}, {%4,%5,%6,%7}, {%8,%9}, {%0,%1,%2,%3};"
        : "+f"(d[0]), "+f"(d[1]), "+f"(d[2]), "+f"(d[3])
        : "r"(a[0]), "r"(a[1]), "r"(a[2]), "r"(a[3]), "r"(b0), "r"(b1));
}

// ---------------------------------------------------------------------------
// Prep: split w_in into bf16 hi/lo, [h][kp], zero pad k>=700
__global__ void prep_w(const float* __restrict__ w_in) {
    int idx = blockIdx.x * blockDim.x + threadIdx.x;
    if (idx >= HH * CP) return;
    int h = idx / CP;
    int k = idx - h * CP;
    float v = (k < CC) ? w_in[h * CC + k] : 0.f;
    __nv_bfloat16 hi = __float2bfloat16(v);
    g_wh[idx] = hi;
    g_wl[idx] = __float2bfloat16(v - __bfloat162float(hi));
}

// Prep: transpose w_rec -> [j][h]
__global__ void prep_wrecT(const float* __restrict__ w_rec) {
    int idx = blockIdx.x * blockDim.x + threadIdx.x;
    if (idx >= HH * HH) return;
    int j = idx >> 10;
    int h = idx & 1023;
    g_wrecT[idx] = w_rec[h * HH + j];
}

// Prep: build delayed input xd[m][c] as bf16 hi/lo, m = t*128 + b
__global__ void build_xd(const float* __restrict__ x, const int* __restrict__ delays) {
    size_t gid = (size_t)blockIdx.x * blockDim.x + threadIdx.x;
    const size_t total = (size_t)MM * CP;
    if (gid >= total) return;
    int c = (int)(gid % CP);
    int m = (int)(gid / CP);
    float v = 0.f;
    if (c < CC) {
        int t = m >> 7;
        int b = m & 127;
        int ts = t - delays[c];
        if (ts >= 0) v = x[((size_t)b * TT + ts) * CC + c];
    }
    __nv_bfloat16 hi = __float2bfloat16(v);
    g_xh[gid] = hi;
    g_xl[gid] = __float2bfloat16(v - __bfloat162float(hi));
}

// ---------------------------------------------------------------------------
// mma.sync split-bf16 GEMM: I_in[M][1024] = xd[M][704] * w_in^T
// CTA 128x128, BK=32, 8 warps (warp tile 32x64), double-buffered cp.async.
// SMEM: per buffer 4 tiles (Ah, Al, Bh, Bl), each 128 rows x 40 bf16 (80B) = 10240B.
#define T_STRIDE 80        // bytes per smem row
#define TILE_BYTES 10240
#define BUF_BYTES  40960
#define GEMM_SMEM  81920
#define NCHUNK 22          // 704/32

__global__ __launch_bounds__(256, 1) void gemm_mma(void) {
    extern __shared__ char smem[];
    const uint32_t sb = smem_u32(smem);
    const int tid = threadIdx.x;
    const int lane = tid & 31;
    const int wid = tid >> 5;
    const int wm = wid & 3;        // 4 warps along M
    const int wn = wid >> 2;       // 2 warps along N
    const int Nb = blockIdx.x * 128;
    const int Mb = blockIdx.y * 128;

    float d[2][8][4];
    #pragma unroll
    for (int i = 0; i < 2; i++)
        #pragma unroll
        for (int j = 0; j < 8; j++)
            #pragma unroll
            for (int q = 0; q < 4; q++) d[i][j][q] = 0.f;

    // cp.async issue of chunk kc into buffer buf (8 x 16B per thread)
    auto load_chunk = [&](int kc, int buf) {
        const int k0 = kc * 32;
        #pragma unroll
        for (int j = 0; j < 2; ++j) {
            int i = tid + 256 * j;
            int r = i >> 2, c = i & 3;
            uint32_t doff = (uint32_t)(r * T_STRIDE + c * 16);
            size_t aoff = (size_t)(Mb + r) * CP + k0 + c * 8;
            size_t boff = (size_t)(Nb + r) * CP + k0 + c * 8;
            uint32_t base = sb + buf * BUF_BYTES + doff;
            CP16(base,                  g_xh + aoff);
            CP16(base + TILE_BYTES,     g_xl + aoff);
            CP16(base + 2 * TILE_BYTES, g_wh + boff);
            CP16(base + 3 * TILE_BYTES, g_wl + boff);
        }
    };

    load_chunk(0, 0); CP_COMMIT();
    load_chunk(1, 1); CP_COMMIT();

    // per-lane ldmatrix address components (byte offsets within a tile)
    const uint32_t a_row = (uint32_t)(wm * 32 + (lane & 15));
    const uint32_t a_kb  = (uint32_t)((lane >> 4) * 16);          // bytes: (lane/16)*8 elems
    const uint32_t b_row = (uint32_t)(wn * 64 + (lane & 7) + ((lane & 16) ? 8 : 0));
    const uint32_t b_kb  = (uint32_t)(((lane >> 3) & 1) * 16);

    for (int kc = 0; kc < NCHUNK; ++kc) {
        const int buf = kc & 1;
        CP_WAIT1();
        __syncthreads();
        const uint32_t Ah = sb + buf * BUF_BYTES;
        const uint32_t Al = Ah + TILE_BYTES;
        const uint32_t Bh = Ah + 2 * TILE_BYTES;
        const uint32_t Bl = Ah + 3 * TILE_BYTES;

        #pragma unroll
        for (int kk = 0; kk < 2; ++kk) {
            const uint32_t kbase = (uint32_t)(kk * 32);  // bytes: kk*16 elems
            uint32_t ah[2][4], al[2][4];
            #pragma unroll
            for (int mf = 0; mf < 2; ++mf) {
                uint32_t ao = (a_row + mf * 16) * T_STRIDE + kbase + a_kb;
                ldsm_x4(ah[mf], Ah + ao);
                ldsm_x4(al[mf], Al + ao);
            }
            uint32_t bh[4][4], bl[4][4];
            #pragma unroll
            for (int nb = 0; nb < 4; ++nb) {
                uint32_t bo = (b_row + nb * 16) * T_STRIDE + kbase + b_kb;
                ldsm_x4(bh[nb], Bh + bo);
                ldsm_x4(bl[nb], Bl + bo);
            }
            #pragma unroll
            for (int mf = 0; mf < 2; ++mf)
                #pragma unroll
                for (int nf = 0; nf < 8; ++nf) {
                    const int nb = nf >> 1, s = (nf & 1) * 2;
                    mma16816(d[mf][nf], ah[mf], bh[nb][s], bh[nb][s + 1]);
                    mma16816(d[mf][nf], ah[mf], bl[nb][s], bl[nb][s + 1]);
                    mma16816(d[mf][nf], al[mf], bh[nb][s], bh[nb][s + 1]);
                }
        }
        __syncthreads();
        if (kc + 2 < NCHUNK) load_chunk(kc + 2, buf);
        CP_COMMIT();
    }

    // Epilogue: store fp32 accumulators
    #pragma unroll
    for (int mf = 0; mf < 2; ++mf) {
        const int row = Mb + wm * 32 + mf * 16 + (lane >> 2);
        #pragma unroll
        for (int nf = 0; nf < 8; ++nf) {
            const int col = Nb + wn * 64 + nf * 8 + (lane & 3) * 2;
            float2* p0 = (float2*)&g_Iin[(size_t)row * HH + col];
            float2* p1 = (float2*)&g_Iin[(size_t)(row + 8) * HH + col];
            *p0 = make_float2(d[mf][nf][0], d[mf][nf][1]);
            *p1 = make_float2(d[mf][nf][2], d[mf][nf][3]);
        }
    }
}

// ---------------------------------------------------------------------------
// Persistent sequential SNN: one CTA per batch, 1024 threads = one per hidden unit.
__global__ __launch_bounds__(1024, 1) void snn_seq(
    const float* __restrict__ w_out,
    const float* __restrict__ alpha, const float* __restrict__ rho,
    const float* __restrict__ beta_a, const float* __restrict__ beta_out,
    float* __restrict__ out)
{
    const int b = blockIdx.x;
    const int h = threadIdx.x;
    const int lane = h & 31;
    const int wid = h >> 5;

    __shared__ int act[HH];
    __shared__ int warp_cnt[32];
    __shared__ int warp_off[32];
    __shared__ int n_act_s;

    float v = 0.f, a = 0.f, spk = 0.f;
    const float al = alpha[h], rh = rho[h], ba = beta_a[h];
    float v_out = 0.f, osum = 0.f;
    float bo = 0.f;
    if (h < OO) bo = beta_out[h];
    int n_act = 0;

    float Icur = g_Iin[(size_t)b * HH + h];   // t = 0 row: m = b

    for (int t = 0; t < TT; ++t) {
        float Inext = 0.f;
        if (t < TT - 1)
            Inext = g_Iin[((size_t)((t + 1) * BB + b)) * HH + h];

        float Irec = 0.f;
        {
            int i = 0;
            for (; i + 4 <= n_act; i += 4) {
                int j0 = act[i], j1 = act[i + 1], j2 = act[i + 2], j3 = act[i + 3];
                Irec += g_wrecT[(size_t)j0 * HH + h];
                Irec += g_wrecT[(size_t)j1 * HH + h];
                Irec += g_wrecT[(size_t)j2 * HH + h];
                Irec += g_wrecT[(size_t)j3 * HH + h];
            }
            for (; i < n_act; ++i)
                Irec += g_wrecT[(size_t)act[i] * HH + h];
        }

        float I1   = Icur + Irec;
        float vn   = al * v * (1.f - spk) + (1.f - al) * (I1 - a);
        float spkn = (vn > 1.0f) ? 1.f : 0.f;
        a = rh * a + (1.f - rh) * (ba * vn + spkn);
        v = vn;
        spk = spkn;

        unsigned msk = __ballot_sync(0xffffffffu, spkn != 0.f);
        if (lane == 0) warp_cnt[wid] = __popc(msk);
        __syncthreads();
        if (wid == 0) {
            int cc = warp_cnt[lane];
            int s = cc;
            #pragma unroll
            for (int dd = 1; dd < 32; dd <<= 1) {
                int y = __shfl_up_sync(0xffffffffu, s, dd);
                if (lane >= dd) s += y;
            }
            warp_off[lane] = s - cc;
            if (lane == 31) n_act_s = s;
        }
        __syncthreads();
        if (spkn != 0.f) {
            int pos = warp_off[wid] + __popc(msk & ((1u << lane) - 1u));
            act[pos] = h;
        }
        __syncthreads();
        n_act = n_act_s;

        if (h < OO) {
            float accum = 0.f;
            for (int i = 0; i < n_act; ++i)
                accum += w_out[h * HH + act[i]];
            v_out = bo * v_out + (1.f - bo) * accum;
            osum += v_out;
        }
        Icur = Inext;
    }

    if (h < OO) out[b * OO + h] = osum * (1.f / (float)TT);
}

// ---------------------------------------------------------------------------
extern "C" void kernel_launch(void* const* d_in, const int* in_sizes, int n_in,
                              void* d_out, int out_size)
{
    const float* x        = (const float*)d_in[0];
    const int*   delays   = (const int*)  d_in[1];
    const float* w_in     = (const float*)d_in[2];
    const float* w_rec    = (const float*)d_in[3];
    const float* w_out    = (const float*)d_in[4];
    const float* alpha    = (const float*)d_in[5];
    const float* rho      = (const float*)d_in[6];
    const float* beta_a   = (const float*)d_in[7];
    const float* beta_out = (const float*)d_in[8];
    float* out = (float*)d_out;

    static bool attr_set = false;
    if (!attr_set) {
        cudaFuncSetAttribute(gemm_mma, cudaFuncAttributeMaxDynamicSharedMemorySize, GEMM_SMEM);
        attr_set = true;
    }

    prep_w    <<<(HH * CP + 255) / 256, 256>>>(w_in);
    prep_wrecT<<<(HH * HH + 255) / 256, 256>>>(w_rec);
    {
        size_t total = (size_t)MM * CP;
        int blocks = (int)((total + 255) / 256);
        build_xd<<<blocks, 256>>>(x, delays);
    }
    {
        dim3 grid(HH / 128, MM / 128);   // (8, 500)
        gemm_mma<<<grid, 256, GEMM_SMEM>>>();
    }
    snn_seq<<<BB, 1024>>>(w_out, alpha, rho, beta_a, beta_out, out);
}

// round 5
// speedup vs baseline: 2.1191x; 1.0903x over previous
#include <cuda_runtime.h>
#include <cuda_bf16.h>
#include <cuda_fp16.h>
#include <cstdint>

// Problem constants
#define TT   500
#define BB   128
#define CC   700
#define CP   704      // padded K
#define HH   1024
#define OO   20
#define MM   (TT*BB)  // 64000

// ---------------------------------------------------------------------------
// Device scratch (no runtime allocation allowed)
__device__ __nv_bfloat16 g_xh[(size_t)MM * CP];   // delayed input hi, row m=(t*128+b)
__device__ __nv_bfloat16 g_xl[(size_t)MM * CP];   // delayed input lo
__device__ __nv_bfloat16 g_wh[(size_t)HH * CP];   // w_in hi  [h][k], K-padded
__device__ __nv_bfloat16 g_wl[(size_t)HH * CP];   // w_in lo
__device__ __half g_wrecH[(size_t)HH * HH];       // w_rec transposed [j][h], fp16
__device__ float g_woutT[(size_t)HH * OO];        // w_out transposed [j][o]
__device__ float g_Iin[(size_t)MM * HH];          // I_in[m][h]

// ---------------------------------------------------------------------------
__device__ __forceinline__ uint32_t smem_u32(const void* p) {
    uint32_t a;
    asm("{ .reg .u64 t; cvta.to.shared.u64 t, %1; cvt.u32.u64 %0, t; }" : "=r"(a) : "l"(p));
    return a;
}
#define CP16(dst, src) asm volatile("cp.async.cg.shared.global [%0], [%1], 16;" :: "r"(dst), "l"(src) : "memory")
#define CP_COMMIT()    asm volatile("cp.async.commit_group;" ::: "memory")
#define CP_WAIT1()     asm volatile("cp.async.wait_group 1;" ::: "memory")

__device__ __forceinline__ void ldsm_x4(uint32_t* r, uint32_t addr) {
    asm volatile("ldmatrix.sync.aligned.m8n8.x4.shared.b16 {%0,%1,%2,%3}, [%4];"
        : "=r"(r[0]), "=r"(r[1]), "=r"(r[2]), "=r"(r[3]) : "r"(addr));
}
__device__ __forceinline__ void mma16816(float* d, const uint32_t* a, uint32_t b0, uint32_t b1) {
    asm volatile(
        "mma.sync.aligned.m16n8k16.row.col.f32.bf16.bf16.f32 "
        "{%0,%1,%2,%3}, {%4,%5,%6,%7}, {%8,%9}, {%0,%1,%2,%3};"
        : "+f"(d[0]), "+f"(d[1]), "+f"(d[2]), "+f"(d[3])
        : "r"(a[0]), "r"(a[1]), "r"(a[2]), "r"(a[3]), "r"(b0), "r"(b1));
}

// ---------------------------------------------------------------------------
// Prep: split w_in into bf16 hi/lo, [h][kp], zero pad k>=700
__global__ void prep_w(const float* __restrict__ w_in) {
    int idx = blockIdx.x * blockDim.x + threadIdx.x;
    if (idx >= HH * CP) return;
    int h = idx / CP;
    int k = idx - h * CP;
    float v = (k < CC) ? w_in[h * CC + k] : 0.f;
    __nv_bfloat16 hi = __float2bfloat16(v);
    g_wh[idx] = hi;
    g_wl[idx] = __float2bfloat16(v - __bfloat162float(hi));
}

// Prep: transpose w_rec -> fp16 [j][h]; transpose w_out -> [j][o]
__global__ void prep_wrec_wout(const float* __restrict__ w_rec,
                               const float* __restrict__ w_out) {
    int idx = blockIdx.x * blockDim.x + threadIdx.x;
    if (idx < HH * HH) {
        int j = idx >> 10;
        int h = idx & 1023;
        g_wrecH[idx] = __float2half(w_rec[h * HH + j]);
    }
    if (idx < HH * OO) {
        int j = idx / OO;
        int o = idx - j * OO;
        g_woutT[idx] = w_out[o * HH + j];
    }
}

// Prep: build delayed input xd[m][c] as bf16 hi/lo, m = t*128 + b
__global__ void build_xd(const float* __restrict__ x, const int* __restrict__ delays) {
    size_t gid = (size_t)blockIdx.x * blockDim.x + threadIdx.x;
    const size_t total = (size_t)MM * CP;
    if (gid >= total) return;
    int c = (int)(gid % CP);
    int m = (int)(gid / CP);
    float v = 0.f;
    if (c < CC) {
        int t = m >> 7;
        int b = m & 127;
        int ts = t - delays[c];
        if (ts >= 0) v = x[((size_t)b * TT + ts) * CC + c];
    }
    __nv_bfloat16 hi = __float2bfloat16(v);
    g_xh[gid] = hi;
    g_xl[gid] = __float2bfloat16(v - __bfloat162float(hi));
}

// ---------------------------------------------------------------------------
// mma.sync split-bf16 GEMM: I_in[M][1024] = xd[M][704] * w_in^T
// CTA 128x128, BK=32, 8 warps (warp tile 32x64), double-buffered cp.async.
// 2 CTAs/SM for latency hiding (regs clamped to 128).
#define T_STRIDE 80        // bytes per smem row
#define TILE_BYTES 10240
#define BUF_BYTES  40960
#define GEMM_SMEM  81920
#define NCHUNK 22          // 704/32

__global__ __launch_bounds__(256, 2) void gemm_mma(void) {
    extern __shared__ char smem[];
    const uint32_t sb = smem_u32(smem);
    const int tid = threadIdx.x;
    const int lane = tid & 31;
    const int wid = tid >> 5;
    const int wm = wid & 3;        // 4 warps along M
    const int wn = wid >> 2;       // 2 warps along N
    const int Nb = blockIdx.x * 128;
    const int Mb = blockIdx.y * 128;

    float d[2][8][4];
    #pragma unroll
    for (int i = 0; i < 2; i++)
        #pragma unroll
        for (int j = 0; j < 8; j++)
            #pragma unroll
            for (int q = 0; q < 4; q++) d[i][j][q] = 0.f;

    // cp.async issue of chunk kc into buffer buf (8 x 16B per thread)
    auto load_chunk = [&](int kc, int buf) {
        const int k0 = kc * 32;
        #pragma unroll
        for (int j = 0; j < 2; ++j) {
            int i = tid + 256 * j;
            int r = i >> 2, c = i & 3;
            uint32_t doff = (uint32_t)(r * T_STRIDE + c * 16);
            size_t aoff = (size_t)(Mb + r) * CP + k0 + c * 8;
            size_t boff = (size_t)(Nb + r) * CP + k0 + c * 8;
            uint32_t base = sb + buf * BUF_BYTES + doff;
            CP16(base,                  g_xh + aoff);
            CP16(base + TILE_BYTES,     g_xl + aoff);
            CP16(base + 2 * TILE_BYTES, g_wh + boff);
            CP16(base + 3 * TILE_BYTES, g_wl + boff);
        }
    };

    load_chunk(0, 0); CP_COMMIT();
    load_chunk(1, 1); CP_COMMIT();

    // per-lane ldmatrix address components (byte offsets within a tile)
    const uint32_t a_row = (uint32_t)(wm * 32 + (lane & 15));
    const uint32_t a_kb  = (uint32_t)((lane >> 4) * 16);
    const uint32_t b_row = (uint32_t)(wn * 64 + (lane & 7) + ((lane & 16) ? 8 : 0));
    const uint32_t b_kb  = (uint32_t)(((lane >> 3) & 1) * 16);

    for (int kc = 0; kc < NCHUNK; ++kc) {
        const int buf = kc & 1;
        CP_WAIT1();
        __syncthreads();
        const uint32_t Ah = sb + buf * BUF_BYTES;
        const uint32_t Al = Ah + TILE_BYTES;
        const uint32_t Bh = Ah + 2 * TILE_BYTES;
        const uint32_t Bl = Ah + 3 * TILE_BYTES;

        #pragma unroll
        for (int kk = 0; kk < 2; ++kk) {
            const uint32_t kbase = (uint32_t)(kk * 32);
            uint32_t ah[2][4], al[2][4];
            #pragma unroll
            for (int mf = 0; mf < 2; ++mf) {
                uint32_t ao = (a_row + mf * 16) * T_STRIDE + kbase + a_kb;
                ldsm_x4(ah[mf], Ah + ao);
                ldsm_x4(al[mf], Al + ao);
            }
            uint32_t bh[4][4], bl[4][4];
            #pragma unroll
            for (int nb = 0; nb < 4; ++nb) {
                uint32_t bo = (b_row + nb * 16) * T_STRIDE + kbase + b_kb;
                ldsm_x4(bh[nb], Bh + bo);
                ldsm_x4(bl[nb], Bl + bo);
            }
            #pragma unroll
            for (int mf = 0; mf < 2; ++mf)
                #pragma unroll
                for (int nf = 0; nf < 8; ++nf) {
                    const int nb = nf >> 1, s = (nf & 1) * 2;
                    mma16816(d[mf][nf], ah[mf], bh[nb][s], bh[nb][s + 1]);
                    mma16816(d[mf][nf], ah[mf], bl[nb][s], bl[nb][s + 1]);
                    mma16816(d[mf][nf], al[mf], bh[nb][s], bh[nb][s + 1]);
                }
        }
        __syncthreads();
        if (kc + 2 < NCHUNK) load_chunk(kc + 2, buf);
        CP_COMMIT();
    }

    // Epilogue: store fp32 accumulators
    #pragma unroll
    for (int mf = 0; mf < 2; ++mf) {
        const int row = Mb + wm * 32 + mf * 16 + (lane >> 2);
        #pragma unroll
        for (int nf = 0; nf < 8; ++nf) {
            const int col = Nb + wn * 64 + nf * 8 + (lane & 3) * 2;
            float2* p0 = (float2*)&g_Iin[(size_t)row * HH + col];
            float2* p1 = (float2*)&g_Iin[(size_t)(row + 8) * HH + col];
            *p0 = make_float2(d[mf][nf][0], d[mf][nf][1]);
            *p1 = make_float2(d[mf][nf][2], d[mf][nf][3]);
        }
    }
}

// ---------------------------------------------------------------------------
// Persistent sequential SNN: one CTA per batch, 1024 threads = one per hidden unit.
// fp16 recurrent weights (half the L2 traffic), 2 barriers per step.
__global__ __launch_bounds__(1024, 1) void snn_seq(
    const float* __restrict__ alpha, const float* __restrict__ rho,
    const float* __restrict__ beta_a, const float* __restrict__ beta_out,
    float* __restrict__ out)
{
    const int b = blockIdx.x;
    const int h = threadIdx.x;
    const int lane = h & 31;
    const int wid = h >> 5;

    __shared__ int act[HH];
    __shared__ int warp_cnt[32];

    float v = 0.f, a = 0.f, spk = 0.f;
    const float al = alpha[h], rh = rho[h], ba = beta_a[h];
    float v_out = 0.f, osum = 0.f;
    float bo = 0.f;
    if (h < OO) bo = beta_out[h];
    int n_act = 0;

    float Icur = g_Iin[(size_t)b * HH + h];   // t = 0 row: m = b
    const __half* __restrict__ wr = g_wrecH;

    for (int t = 0; t < TT; ++t) {
        float Inext = 0.f;
        if (t < TT - 1)
            Inext = g_Iin[((size_t)((t + 1) * BB + b)) * HH + h];

        // sparse recurrent input (fp16 rows, fp32 accumulate)
        float Irec = 0.f;
        {
            int i = 0;
            for (; i + 4 <= n_act; i += 4) {
                int j0 = act[i], j1 = act[i + 1], j2 = act[i + 2], j3 = act[i + 3];
                Irec += __half2float(wr[(size_t)j0 * HH + h]);
                Irec += __half2float(wr[(size_t)j1 * HH + h]);
                Irec += __half2float(wr[(size_t)j2 * HH + h]);
                Irec += __half2float(wr[(size_t)j3 * HH + h]);
            }
            for (; i < n_act; ++i)
                Irec += __half2float(wr[(size_t)act[i] * HH + h]);
        }

        float I1   = Icur + Irec;
        float vn   = al * v * (1.f - spk) + (1.f - al) * (I1 - a);
        float spkn = (vn > 1.0f) ? 1.f : 0.f;
        a = rh * a + (1.f - rh) * (ba * vn + spkn);
        v = vn;
        spk = spkn;

        // 2-barrier deterministic compaction
        unsigned msk = __ballot_sync(0xffffffffu, spkn != 0.f);
        if (lane == 0) warp_cnt[wid] = __popc(msk);
        __syncthreads();                          // warp_cnt ready; prev act reads done
        {
            int cnt = warp_cnt[lane];
            int incl = cnt;
            #pragma unroll
            for (int dd = 1; dd < 32; dd <<= 1) {
                int y = __shfl_up_sync(0xffffffffu, incl, dd);
                if (lane >= dd) incl += y;
            }
            int total  = __shfl_sync(0xffffffffu, incl, 31);
            int excl   = incl - cnt;
            int my_off = __shfl_sync(0xffffffffu, excl, wid);
            if (spkn != 0.f)
                act[my_off + __popc(msk & ((1u << lane) - 1u))] = h;
            n_act = total;
        }
        __syncthreads();                          // new act complete

        // readout: 20 threads, contiguous 80B rows of w_outT
        if (h < OO) {
            float accum = 0.f;
            for (int i = 0; i < n_act; ++i)
                accum += g_woutT[(size_t)act[i] * OO + h];
            v_out = bo * v_out + (1.f - bo) * accum;
            osum += v_out;
        }
        Icur = Inext;
    }

    if (h < OO) out[b * OO + h] = osum * (1.f / (float)TT);
}

// ---------------------------------------------------------------------------
extern "C" void kernel_launch(void* const* d_in, const int* in_sizes, int n_in,
                              void* d_out, int out_size)
{
    const float* x        = (const float*)d_in[0];
    const int*   delays   = (const int*)  d_in[1];
    const float* w_in     = (const float*)d_in[2];
    const float* w_rec    = (const float*)d_in[3];
    const float* w_out    = (const float*)d_in[4];
    const float* alpha    = (const float*)d_in[5];
    const float* rho      = (const float*)d_in[6];
    const float* beta_a   = (const float*)d_in[7];
    const float* beta_out = (const float*)d_in[8];
    float* out = (float*)d_out;

    static bool attr_set = false;
    if (!attr_set) {
        cudaFuncSetAttribute(gemm_mma, cudaFuncAttributeMaxDynamicSharedMemorySize, GEMM_SMEM);
        attr_set = true;
    }

    prep_w        <<<(HH * CP + 255) / 256, 256>>>(w_in);
    prep_wrec_wout<<<(HH * HH + 255) / 256, 256>>>(w_rec, w_out);
    {
        size_t total = (size_t)MM * CP;
        int blocks = (int)((total + 255) / 256);
        build_xd<<<blocks, 256>>>(x, delays);
    }
    {
        dim3 grid(HH / 128, MM / 128);   // (8, 500)
        gemm_mma<<<grid, 256, GEMM_SMEM>>>();
    }
    snn_seq<<<BB, 1024>>>(alpha, rho, beta_a, beta_out, out);
}

// round 10
// speedup vs baseline: 2.1604x; 1.0195x over previous
#include <cuda_runtime.h>
#include <cuda_bf16.h>
#include <cuda_fp16.h>
#include <cstdint>

// Problem constants
#define TT   500
#define BB   128
#define CC   700
#define CP   704      // padded K
#define HH   1024
#define OO   20
#define MM   (TT*BB)  // 64000

// ---------------------------------------------------------------------------
// Device scratch
__device__ __nv_bfloat16 g_xh[(size_t)MM * CP];   // delayed input hi
__device__ __nv_bfloat16 g_xl[(size_t)MM * CP];   // delayed input lo
__device__ __nv_bfloat16 g_wh[(size_t)HH * CP];   // w_in hi  [h][k]
__device__ __nv_bfloat16 g_wl[(size_t)HH * CP];   // w_in lo
__device__ __half g_wrecH[(size_t)HH * HH];       // w_rec transposed [j][h], fp16
__device__ float g_woutT[(size_t)HH * OO];        // w_out transposed [j][o]
__device__ float g_Iin[(size_t)MM * HH];          // I_in[m][h]

// ---------------------------------------------------------------------------
__device__ __forceinline__ uint32_t smem_u32(const void* p) {
    uint32_t a;
    asm("{ .reg .u64 t; cvta.to.shared.u64 t, %1; cvt.u32.u64 %0, t; }" : "=r"(a) : "l"(p));
    return a;
}
#define CP16(dst, src) asm volatile("cp.async.cg.shared.global [%0], [%1], 16;" :: "r"(dst), "l"(src) : "memory")
#define CP_COMMIT()    asm volatile("cp.async.commit_group;" ::: "memory")
#define CP_WAITG2()    asm volatile("cp.async.wait_group 2;" ::: "memory")

__device__ __forceinline__ void ldsm_x4(uint32_t* r, uint32_t addr) {
    asm volatile("ldmatrix.sync.aligned.m8n8.x4.shared.b16 {%0,%1,%2,%3}, [%4];"
        : "=r"(r[0]), "=r"(r[1]), "=r"(r[2]), "=r"(r[3]) : "r"(addr));
}
__device__ __forceinline__ void mma16816(float* d, const uint32_t* a, uint32_t b0, uint32_t b1) {
    asm volatile(
        "mma.sync.aligned.m16n8k16.row.col.f32.bf16.bf16.f32 "
        "{%0,%1,%2,%3}, {%4,%5,%6,%7}, {%8,%9}, {%0,%1,%2,%3};"
        : "+f"(d[0]), "+f"(d[1]), "+f"(d[2]), "+f"(d[3])
        : "r"(a[0]), "r"(a[1]), "r"(a[2]), "r"(a[3]), "r"(b0), "r"(b1));
}

// ---------------------------------------------------------------------------
// Prep: split w_in into bf16 hi/lo, [h][kp], zero pad k>=700
__global__ void prep_w(const float* __restrict__ w_in) {
    int idx = blockIdx.x * blockDim.x + threadIdx.x;
    if (idx >= HH * CP) return;
    int h = idx / CP;
    int k = idx - h * CP;
    float v = (k < CC) ? w_in[h * CC + k] : 0.f;
    __nv_bfloat16 hi = __float2bfloat16(v);
    g_wh[idx] = hi;
    g_wl[idx] = __float2bfloat16(v - __bfloat162float(hi));
}

// Prep: transpose w_rec -> fp16 [j][h]; transpose w_out -> [j][o]
__global__ void prep_wrec_wout(const float* __restrict__ w_rec,
                               const float* __restrict__ w_out) {
    int idx = blockIdx.x * blockDim.x + threadIdx.x;
    if (idx < HH * HH) {
        int j = idx >> 10;
        int h = idx & 1023;
        g_wrecH[idx] = __float2half(w_rec[h * HH + j]);
    }
    if (idx < HH * OO) {
        int j = idx / OO;
        int o = idx - j * OO;
        g_woutT[idx] = w_out[o * HH + j];
    }
}

// ---------------------------------------------------------------------------
// build_xd tiled: block handles (c-tile 128, t-tile 128, batch b).
#define XT 128              // t-tile
#define XC 128              // c-tile
#define XROWS (XT + 30)     // 158
#define XD_SMEM (XROWS * XC * 4)   // 80896 B

__global__ __launch_bounds__(256) void build_xd(const float* __restrict__ x,
                                                const int* __restrict__ delays) {
    extern __shared__ float sx[];   // [XROWS][XC]
    __shared__ int sd[XC];

    const int c0 = blockIdx.x * XC;
    const int t0 = blockIdx.y * XT;
    const int b  = blockIdx.z;
    const int tid = threadIdx.x;

    if (tid < XC) {
        int c = c0 + tid;
        sd[tid] = (c < CC) ? delays[c] : 0;
    }

    // load tile (rows t0-30 .. t0+XT-1), zero out-of-range. 158*128 = 79*256 exactly.
    const float* xb = x + (size_t)b * TT * CC;
    #pragma unroll
    for (int it = 0; it < (XROWS * XC) / 256; ++it) {
        int idx = it * 256 + tid;
        int row = idx >> 7;
        int col = idx & 127;
        int g = t0 - 30 + row;
        int c = c0 + col;
        float v = 0.f;
        if (g >= 0 && g < TT && c < CC)
            v = xb[(size_t)g * CC + c];
        sx[row * XC + col] = v;
    }
    __syncthreads();

    // write delayed outputs (guard c0+col < CP: last c-tile covers 640..767 but
    // rows are only CP=704 long — writing past 703 corrupts the next m-row!)
    #pragma unroll
    for (int it = 0; it < (XT * XC) / 256; ++it) {
        int idx = it * 256 + tid;
        int tt = idx >> 7;
        int col = idx & 127;
        int t = t0 + tt;
        if (t >= TT || c0 + col >= CP) continue;
        float v = sx[(tt + 30 - sd[col]) * XC + col];
        __nv_bfloat16 hi = __float2bfloat16(v);
        __nv_bfloat16 lo = __float2bfloat16(v - __bfloat162float(hi));
        size_t o = (size_t)(t * BB + b) * CP + c0 + col;
        g_xh[o] = hi;
        g_xl[o] = lo;
    }
}

// ---------------------------------------------------------------------------
// bf16 3-pass GEMM, 512 threads, CTA tile 128x128, BK=64, 3-stage cp.async.
// 16 warps as 4(M) x 4(N), warp tile 32x32.
#define G_STRIDE 144
#define G_PLANE  (128 * G_STRIDE)      // 18432
#define G_STAGE  (4 * G_PLANE)         // 73728
#define G_SMEM   (3 * G_STAGE)         // 221184
#define NCHUNK   11                    // 704/64

__global__ __launch_bounds__(512) void gemm_mma(void) {
    extern __shared__ char smem[];
    const uint32_t sb = smem_u32(smem);
    const int tid = threadIdx.x;
    const int lane = tid & 31;
    const int wid = tid >> 5;
    const int wm = wid & 3;        // 4 warps along M
    const int wn = wid >> 2;       // 4 warps along N
    const int Nb = blockIdx.x * 128;
    const int Mb = blockIdx.y * 128;

    float d[2][4][4];
    #pragma unroll
    for (int i = 0; i < 2; i++)
        #pragma unroll
        for (int j = 0; j < 4; j++)
            #pragma unroll
            for (int q = 0; q < 4; q++) d[i][j][q] = 0.f;

    auto load_chunk = [&](int kc, int s) {
        const int k0 = kc * 64;
        const uint32_t base = sb + s * G_STAGE;
        #pragma unroll
        for (int j = 0; j < 2; ++j) {
            int i = tid + 512 * j;
            int r = i >> 3, c = i & 7;
            uint32_t doff = (uint32_t)(r * G_STRIDE + c * 16);
            size_t aoff = (size_t)(Mb + r) * CP + k0 + c * 8;
            size_t boff = (size_t)(Nb + r) * CP + k0 + c * 8;
            CP16(base + doff,               g_xh + aoff);
            CP16(base + G_PLANE + doff,     g_xl + aoff);
            CP16(base + 2 * G_PLANE + doff, g_wh + boff);
            CP16(base + 3 * G_PLANE + doff, g_wl + boff);
        }
    };

    load_chunk(0, 0); CP_COMMIT();
    load_chunk(1, 1); CP_COMMIT();

    const uint32_t a_row = (uint32_t)(wm * 32 + (lane & 15));
    const uint32_t a_kb  = (uint32_t)((lane >> 4) * 16);
    const uint32_t b_row = (uint32_t)(wn * 32 + (lane & 7) + ((lane & 16) ? 8 : 0));
    const uint32_t b_kb  = (uint32_t)(((lane >> 3) & 1) * 16);

    for (int kc = 0; kc < NCHUNK; ++kc) {
        const int s = kc % 3;
        if (kc + 2 < NCHUNK) load_chunk(kc + 2, (kc + 2) % 3);
        CP_COMMIT();
        CP_WAITG2();                 // chunk kc complete
        __syncthreads();

        const uint32_t Ah = sb + s * G_STAGE;
        const uint32_t Al = Ah + G_PLANE;
        const uint32_t Bh = Ah + 2 * G_PLANE;
        const uint32_t Bl = Ah + 3 * G_PLANE;

        #pragma unroll
        for (int kk = 0; kk < 4; ++kk) {
            const uint32_t kbase = (uint32_t)(kk * 32);
            uint32_t ah[2][4], al[2][4];
            #pragma unroll
            for (int mf = 0; mf < 2; ++mf) {
                uint32_t ao = (a_row + mf * 16) * G_STRIDE + kbase + a_kb;
                ldsm_x4(ah[mf], Ah + ao);
                ldsm_x4(al[mf], Al + ao);
            }
            uint32_t bh[2][4], bl[2][4];
            #pragma unroll
            for (int nb = 0; nb < 2; ++nb) {
                uint32_t bo = (b_row + nb * 16) * G_STRIDE + kbase + b_kb;
                ldsm_x4(bh[nb], Bh + bo);
                ldsm_x4(bl[nb], Bl + bo);
            }
            #pragma unroll
            for (int mf = 0; mf < 2; ++mf)
                #pragma unroll
                for (int nf = 0; nf < 4; ++nf) {
                    const int nb = nf >> 1, q = (nf & 1) * 2;
                    mma16816(d[mf][nf], ah[mf], bh[nb][q], bh[nb][q + 1]);
                    mma16816(d[mf][nf], ah[mf], bl[nb][q], bl[nb][q + 1]);
                    mma16816(d[mf][nf], al[mf], bh[nb][q], bh[nb][q + 1]);
                }
        }
        __syncthreads();
    }

    // Epilogue
    #pragma unroll
    for (int mf = 0; mf < 2; ++mf) {
        const int row = Mb + wm * 32 + mf * 16 + (lane >> 2);
        #pragma unroll
        for (int nf = 0; nf < 4; ++nf) {
            const int col = Nb + wn * 32 + nf * 8 + (lane & 3) * 2;
            float2* p0 = (float2*)&g_Iin[(size_t)row * HH + col];
            float2* p1 = (float2*)&g_Iin[(size_t)(row + 8) * HH + col];
            *p0 = make_float2(d[mf][nf][0], d[mf][nf][1]);
            *p1 = make_float2(d[mf][nf][2], d[mf][nf][3]);
        }
    }
}

// ---------------------------------------------------------------------------
// Persistent sequential SNN (unchanged — proven bit-exact)
__global__ __launch_bounds__(1024, 1) void snn_seq(
    const float* __restrict__ alpha, const float* __restrict__ rho,
    const float* __restrict__ beta_a, const float* __restrict__ beta_out,
    float* __restrict__ out)
{
    const int b = blockIdx.x;
    const int h = threadIdx.x;
    const int lane = h & 31;
    const int wid = h >> 5;

    __shared__ int act[HH];
    __shared__ int warp_cnt[32];

    float v = 0.f, a = 0.f, spk = 0.f;
    const float al = alpha[h], rh = rho[h], ba = beta_a[h];
    float v_out = 0.f, osum = 0.f;
    float bo = 0.f;
    if (h < OO) bo = beta_out[h];
    int n_act = 0;

    float Icur = g_Iin[(size_t)b * HH + h];
    const __half* __restrict__ wr = g_wrecH;

    for (int t = 0; t < TT; ++t) {
        float Inext = 0.f;
        if (t < TT - 1)
            Inext = g_Iin[((size_t)((t + 1) * BB + b)) * HH + h];

        float Irec = 0.f;
        {
            int i = 0;
            for (; i + 4 <= n_act; i += 4) {
                int j0 = act[i], j1 = act[i + 1], j2 = act[i + 2], j3 = act[i + 3];
                Irec += __half2float(wr[(size_t)j0 * HH + h]);
                Irec += __half2float(wr[(size_t)j1 * HH + h]);
                Irec += __half2float(wr[(size_t)j2 * HH + h]);
                Irec += __half2float(wr[(size_t)j3 * HH + h]);
            }
            for (; i < n_act; ++i)
                Irec += __half2float(wr[(size_t)act[i] * HH + h]);
        }

        float I1   = Icur + Irec;
        float vn   = al * v * (1.f - spk) + (1.f - al) * (I1 - a);
        float spkn = (vn > 1.0f) ? 1.f : 0.f;
        a = rh * a + (1.f - rh) * (ba * vn + spkn);
        v = vn;
        spk = spkn;

        unsigned msk = __ballot_sync(0xffffffffu, spkn != 0.f);
        if (lane == 0) warp_cnt[wid] = __popc(msk);
        __syncthreads();
        {
            int cnt = warp_cnt[lane];
            int incl = cnt;
            #pragma unroll
            for (int dd = 1; dd < 32; dd <<= 1) {
                int y = __shfl_up_sync(0xffffffffu, incl, dd);
                if (lane >= dd) incl += y;
            }
            int total  = __shfl_sync(0xffffffffu, incl, 31);
            int excl   = incl - cnt;
            int my_off = __shfl_sync(0xffffffffu, excl, wid);
            if (spkn != 0.f)
                act[my_off + __popc(msk & ((1u << lane) - 1u))] = h;
            n_act = total;
        }
        __syncthreads();

        if (h < OO) {
            float accum = 0.f;
            for (int i = 0; i < n_act; ++i)
                accum += g_woutT[(size_t)act[i] * OO + h];
            v_out = bo * v_out + (1.f - bo) * accum;
            osum += v_out;
        }
        Icur = Inext;
    }

    if (h < OO) out[b * OO + h] = osum * (1.f / (float)TT);
}

// ---------------------------------------------------------------------------
extern "C" void kernel_launch(void* const* d_in, const int* in_sizes, int n_in,
                              void* d_out, int out_size)
{
    const float* x        = (const float*)d_in[0];
    const int*   delays   = (const int*)  d_in[1];
    const float* w_in     = (const float*)d_in[2];
    const float* w_rec    = (const float*)d_in[3];
    const float* w_out    = (const float*)d_in[4];
    const float* alpha    = (const float*)d_in[5];
    const float* rho      = (const float*)d_in[6];
    const float* beta_a   = (const float*)d_in[7];
    const float* beta_out = (const float*)d_in[8];
    float* out = (float*)d_out;

    static bool attr_set = false;
    if (!attr_set) {
        cudaFuncSetAttribute(gemm_mma, cudaFuncAttributeMaxDynamicSharedMemorySize, G_SMEM);
        cudaFuncSetAttribute(build_xd, cudaFuncAttributeMaxDynamicSharedMemorySize, XD_SMEM);
        attr_set = true;
    }

    prep_w        <<<(HH * CP + 255) / 256, 256>>>(w_in);
    prep_wrec_wout<<<(HH * HH + 255) / 256, 256>>>(w_rec, w_out);
    {
        dim3 grid((CP + XC - 1) / XC, (TT + XT - 1) / XT, BB);  // (6,4,128)
        build_xd<<<grid, 256, XD_SMEM>>>(x, delays);
    }
    {
        dim3 grid(HH / 128, MM / 128);   // (8, 500)
        gemm_mma<<<grid, 512, G_SMEM>>>();
    }
    snn_seq<<<BB, 1024>>>(alpha, rho, beta_a, beta_out, out);
}

// round 11
// speedup vs baseline: 2.4360x; 1.1276x over previous
#include <cuda_runtime.h>
#include <cuda_bf16.h>
#include <cuda_fp16.h>
#include <cstdint>

// Problem constants
#define TT   500
#define BB   128
#define CC   700
#define CP   704      // padded K
#define HH   1024
#define OO   20
#define MM   (TT*BB)  // 64000

// ---------------------------------------------------------------------------
// Device scratch
__device__ __nv_bfloat16 g_xh[(size_t)MM * CP];   // delayed input hi
__device__ __nv_bfloat16 g_xl[(size_t)MM * CP];   // delayed input lo
__device__ __nv_bfloat16 g_wh[(size_t)HH * CP];   // w_in hi  [h][k]
__device__ __nv_bfloat16 g_wl[(size_t)HH * CP];   // w_in lo
__device__ __half g_wrecH[(size_t)HH * HH];       // w_rec transposed [j][h], fp16
__device__ float g_woutT[(size_t)HH * OO];        // w_out transposed [j][o]
__device__ float g_Iin[(size_t)MM * HH];          // I_in[m][h]
__device__ int   g_done[TT];                      // per-timestep tile counters

// ---------------------------------------------------------------------------
__device__ __forceinline__ uint32_t smem_u32(const void* p) {
    uint32_t a;
    asm("{ .reg .u64 t; cvta.to.shared.u64 t, %1; cvt.u32.u64 %0, t; }" : "=r"(a) : "l"(p));
    return a;
}
#define CP16(dst, src) asm volatile("cp.async.cg.shared.global [%0], [%1], 16;" :: "r"(dst), "l"(src) : "memory")
#define CP_COMMIT()    asm volatile("cp.async.commit_group;" ::: "memory")
#define CP_WAIT1()     asm volatile("cp.async.wait_group 1;" ::: "memory")

__device__ __forceinline__ void ldsm_x4(uint32_t* r, uint32_t addr) {
    asm volatile("ldmatrix.sync.aligned.m8n8.x4.shared.b16 {%0,%1,%2,%3}, [%4];"
        : "=r"(r[0]), "=r"(r[1]), "=r"(r[2]), "=r"(r[3]) : "r"(addr));
}
__device__ __forceinline__ void mma16816(float* d, const uint32_t* a, uint32_t b0, uint32_t b1) {
    asm volatile(
        "mma.sync.aligned.m16n8k16.row.col.f32.bf16.bf16.f32 "
        "{%0,%1,%2,%3}, {%4,%5,%6,%7}, {%8,%9}, {%0,%1,%2,%3};"
        : "+f"(d[0]), "+f"(d[1]), "+f"(d[2]), "+f"(d[3])
        : "r"(a[0]), "r"(a[1]), "r"(a[2]), "r"(a[3]), "r"(b0), "r"(b1));
}

// ---------------------------------------------------------------------------
__global__ void zero_flags(void) {
    int i = threadIdx.x;
    if (i < TT) g_done[i] = 0;
    if (i + 512 < TT) g_done[i + 512] = 0;
}

// Prep: split w_in into bf16 hi/lo, [h][kp], zero pad k>=700
__global__ void prep_w(const float* __restrict__ w_in) {
    int idx = blockIdx.x * blockDim.x + threadIdx.x;
    if (idx >= HH * CP) return;
    int h = idx / CP;
    int k = idx - h * CP;
    float v = (k < CC) ? w_in[h * CC + k] : 0.f;
    __nv_bfloat16 hi = __float2bfloat16(v);
    g_wh[idx] = hi;
    g_wl[idx] = __float2bfloat16(v - __bfloat162float(hi));
}

// Prep: transpose w_rec -> fp16 [j][h]; transpose w_out -> [j][o]
__global__ void prep_wrec_wout(const float* __restrict__ w_rec,
                               const float* __restrict__ w_out) {
    int idx = blockIdx.x * blockDim.x + threadIdx.x;
    if (idx < HH * HH) {
        int j = idx >> 10;
        int h = idx & 1023;
        g_wrecH[idx] = __float2half(w_rec[h * HH + j]);
    }
    if (idx < HH * OO) {
        int j = idx / OO;
        int o = idx - j * OO;
        g_woutT[idx] = w_out[o * HH + j];
    }
}

// ---------------------------------------------------------------------------
// build_xd tiled (proven correct in R10)
#define XT 128
#define XC 128
#define XROWS (XT + 30)     // 158
#define XD_SMEM (XROWS * XC * 4)

__global__ __launch_bounds__(256) void build_xd(const float* __restrict__ x,
                                                const int* __restrict__ delays) {
    extern __shared__ float sx[];
    __shared__ int sd[XC];

    const int c0 = blockIdx.x * XC;
    const int t0 = blockIdx.y * XT;
    const int b  = blockIdx.z;
    const int tid = threadIdx.x;

    if (tid < XC) {
        int c = c0 + tid;
        sd[tid] = (c < CC) ? delays[c] : 0;
    }
    const float* xb = x + (size_t)b * TT * CC;
    #pragma unroll
    for (int it = 0; it < (XROWS * XC) / 256; ++it) {
        int idx = it * 256 + tid;
        int row = idx >> 7;
        int col = idx & 127;
        int g = t0 - 30 + row;
        int c = c0 + col;
        float v = 0.f;
        if (g >= 0 && g < TT && c < CC)
            v = xb[(size_t)g * CC + c];
        sx[row * XC + col] = v;
    }
    __syncthreads();
    #pragma unroll
    for (int it = 0; it < (XT * XC) / 256; ++it) {
        int idx = it * 256 + tid;
        int tt = idx >> 7;
        int col = idx & 127;
        int t = t0 + tt;
        if (t >= TT || c0 + col >= CP) continue;
        float v = sx[(tt + 30 - sd[col]) * XC + col];
        __nv_bfloat16 hi = __float2bfloat16(v);
        __nv_bfloat16 lo = __float2bfloat16(v - __bfloat162float(hi));
        size_t o = (size_t)(t * BB + b) * CP + c0 + col;
        g_xh[o] = hi;
        g_xl[o] = lo;
    }
}

// ---------------------------------------------------------------------------
// Fused kernel: bids 0..127 = SNN consumers (b = bid), bids 128..4127 = GEMM
// producers (R5-config GEMM, tile by = t). 256 threads, 80KB smem, 2 CTAs/SM.
#define T_STRIDE 80
#define TILE_BYTES 10240
#define BUF_BYTES  40960
#define FUSED_SMEM 81920
#define NCHUNK 22          // 704/32
#define NGTILE_N 8         // N tiles per timestep

__device__ __forceinline__ void gemm_body(char* smem, int gid) {
    const uint32_t sb = smem_u32(smem);
    const int tid = threadIdx.x;
    const int lane = tid & 31;
    const int wid = tid >> 5;
    const int wm = wid & 3;        // 4 warps along M
    const int wn = wid >> 2;       // 2 warps along N
    const int by = gid >> 3;       // timestep t
    const int Nb = (gid & 7) * 128;
    const int Mb = by * 128;

    float d[2][8][4];
    #pragma unroll
    for (int i = 0; i < 2; i++)
        #pragma unroll
        for (int j = 0; j < 8; j++)
            #pragma unroll
            for (int q = 0; q < 4; q++) d[i][j][q] = 0.f;

    auto load_chunk = [&](int kc, int buf) {
        const int k0 = kc * 32;
        #pragma unroll
        for (int j = 0; j < 2; ++j) {
            int i = tid + 256 * j;
            int r = i >> 2, c = i & 3;
            uint32_t doff = (uint32_t)(r * T_STRIDE + c * 16);
            size_t aoff = (size_t)(Mb + r) * CP + k0 + c * 8;
            size_t boff = (size_t)(Nb + r) * CP + k0 + c * 8;
            uint32_t base = sb + buf * BUF_BYTES + doff;
            CP16(base,                  g_xh + aoff);
            CP16(base + TILE_BYTES,     g_xl + aoff);
            CP16(base + 2 * TILE_BYTES, g_wh + boff);
            CP16(base + 3 * TILE_BYTES, g_wl + boff);
        }
    };

    load_chunk(0, 0); CP_COMMIT();
    load_chunk(1, 1); CP_COMMIT();

    const uint32_t a_row = (uint32_t)(wm * 32 + (lane & 15));
    const uint32_t a_kb  = (uint32_t)((lane >> 4) * 16);
    const uint32_t b_row = (uint32_t)(wn * 64 + (lane & 7) + ((lane & 16) ? 8 : 0));
    const uint32_t b_kb  = (uint32_t)(((lane >> 3) & 1) * 16);

    for (int kc = 0; kc < NCHUNK; ++kc) {
        const int buf = kc & 1;
        CP_WAIT1();
        __syncthreads();
        const uint32_t Ah = sb + buf * BUF_BYTES;
        const uint32_t Al = Ah + TILE_BYTES;
        const uint32_t Bh = Ah + 2 * TILE_BYTES;
        const uint32_t Bl = Ah + 3 * TILE_BYTES;

        #pragma unroll
        for (int kk = 0; kk < 2; ++kk) {
            const uint32_t kbase = (uint32_t)(kk * 32);
            uint32_t ah[2][4], al[2][4];
            #pragma unroll
            for (int mf = 0; mf < 2; ++mf) {
                uint32_t ao = (a_row + mf * 16) * T_STRIDE + kbase + a_kb;
                ldsm_x4(ah[mf], Ah + ao);
                ldsm_x4(al[mf], Al + ao);
            }
            uint32_t bh[4][4], bl[4][4];
            #pragma unroll
            for (int nb = 0; nb < 4; ++nb) {
                uint32_t bo = (b_row + nb * 16) * T_STRIDE + kbase + b_kb;
                ldsm_x4(bh[nb], Bh + bo);
                ldsm_x4(bl[nb], Bl + bo);
            }
            #pragma unroll
            for (int mf = 0; mf < 2; ++mf)
                #pragma unroll
                for (int nf = 0; nf < 8; ++nf) {
                    const int nb = nf >> 1, s = (nf & 1) * 2;
                    mma16816(d[mf][nf], ah[mf], bh[nb][s], bh[nb][s + 1]);
                    mma16816(d[mf][nf], ah[mf], bl[nb][s], bl[nb][s + 1]);
                    mma16816(d[mf][nf], al[mf], bh[nb][s], bh[nb][s + 1]);
                }
        }
        __syncthreads();
        if (kc + 2 < NCHUNK) load_chunk(kc + 2, buf);
        CP_COMMIT();
    }

    #pragma unroll
    for (int mf = 0; mf < 2; ++mf) {
        const int row = Mb + wm * 32 + mf * 16 + (lane >> 2);
        #pragma unroll
        for (int nf = 0; nf < 8; ++nf) {
            const int col = Nb + wn * 64 + nf * 8 + (lane & 3) * 2;
            float2* p0 = (float2*)&g_Iin[(size_t)row * HH + col];
            float2* p1 = (float2*)&g_Iin[(size_t)(row + 8) * HH + col];
            *p0 = make_float2(d[mf][nf][0], d[mf][nf][1]);
            *p1 = make_float2(d[mf][nf][2], d[mf][nf][3]);
        }
    }

    // publish: all stores visible, then count this tile for timestep by
    __threadfence();
    __syncthreads();
    if (tid == 0) atomicAdd(&g_done[by], 1);
}

__device__ __forceinline__ void snn_body(
    char* smem,
    const float* __restrict__ alpha, const float* __restrict__ rho,
    const float* __restrict__ beta_a, const float* __restrict__ beta_out,
    float* __restrict__ out)
{
    const int b = blockIdx.x;           // 0..127
    const int tid = threadIdx.x;        // 256 threads, 4 hidden units each
    const int lane = tid & 31;
    const int wid = tid >> 5;           // 8 warps

    int* act = (int*)smem;              // [HH]
    int* chunk_cnt = act + HH;          // [32]

    float v[4], aa[4], spk[4], al[4], rh[4], ba[4];
    #pragma unroll
    for (int k = 0; k < 4; ++k) {
        int h = tid + 256 * k;
        v[k] = 0.f; aa[k] = 0.f; spk[k] = 0.f;
        al[k] = alpha[h]; rh[k] = rho[h]; ba[k] = beta_a[h];
    }
    float v_out = 0.f, osum = 0.f, bo = 0.f;
    if (tid < OO) bo = beta_out[tid];
    int n_act = 0;

    const __half* __restrict__ wr = g_wrecH;

    for (int t = 0; t < TT; ++t) {
        // wait until all 8 N-tiles of timestep t are published
        if (tid == 0) {
            int dv;
            do {
                asm volatile("ld.acquire.gpu.global.b32 %0, [%1];"
                             : "=r"(dv) : "l"(&g_done[t]) : "memory");
                if (dv < NGTILE_N) __nanosleep(200);
            } while (dv < NGTILE_N);
        }
        __syncthreads();                                  // S0

        const float* Irow = &g_Iin[(size_t)(t * BB + b) * HH];
        float Icur[4];
        #pragma unroll
        for (int k = 0; k < 4; ++k) Icur[k] = Irow[tid + 256 * k];

        // sparse recurrent input over previous step's active list
        float Irec[4] = {0.f, 0.f, 0.f, 0.f};
        for (int i = 0; i < n_act; ++i) {
            const __half* row = wr + (size_t)act[i] * HH + tid;
            #pragma unroll
            for (int k = 0; k < 4; ++k)
                Irec[k] += __half2float(row[256 * k]);
        }

        // LIF update
        float spkn[4];
        #pragma unroll
        for (int k = 0; k < 4; ++k) {
            float I1 = Icur[k] + Irec[k];
            float vn = al[k] * v[k] * (1.f - spk[k]) + (1.f - al[k]) * (I1 - aa[k]);
            spkn[k] = (vn > 1.0f) ? 1.f : 0.f;
            aa[k] = rh[k] * aa[k] + (1.f - rh[k]) * (ba[k] * vn + spkn[k]);
            v[k] = vn;
            spk[k] = spkn[k];
        }

        // deterministic compaction: chunk (k,wid) covers h in ascending order
        unsigned msk[4];
        #pragma unroll
        for (int k = 0; k < 4; ++k) {
            msk[k] = __ballot_sync(0xffffffffu, spkn[k] != 0.f);
            if (lane == 0) chunk_cnt[k * 8 + wid] = __popc(msk[k]);
        }
        __syncthreads();                                  // S1 (old act reads done)
        {
            int cnt = chunk_cnt[lane];
            int incl = cnt;
            #pragma unroll
            for (int dd = 1; dd < 32; dd <<= 1) {
                int y = __shfl_up_sync(0xffffffffu, incl, dd);
                if (lane >= dd) incl += y;
            }
            int excl = incl - cnt;
            n_act = __shfl_sync(0xffffffffu, incl, 31);
            #pragma unroll
            for (int k = 0; k < 4; ++k) {
                int off = __shfl_sync(0xffffffffu, excl, k * 8 + wid);
                if (spkn[k] != 0.f)
                    act[off + __popc(msk[k] & ((1u << lane) - 1u))] = tid + 256 * k;
            }
        }
        __syncthreads();                                  // S2 (new act ready)

        // readout over NEW active list
        if (tid < OO) {
            float accum = 0.f;
            for (int i = 0; i < n_act; ++i)
                accum += g_woutT[(size_t)act[i] * OO + tid];
            v_out = bo * v_out + (1.f - bo) * accum;
            osum += v_out;
        }
    }

    if (tid < OO) out[b * OO + tid] = osum * (1.f / (float)TT);
}

__global__ __launch_bounds__(256, 2) void fused(
    const float* __restrict__ alpha, const float* __restrict__ rho,
    const float* __restrict__ beta_a, const float* __restrict__ beta_out,
    float* __restrict__ out)
{
    extern __shared__ char smem[];
    if (blockIdx.x < BB)
        snn_body(smem, alpha, rho, beta_a, beta_out, out);
    else
        gemm_body(smem, blockIdx.x - BB);
}

// ---------------------------------------------------------------------------
extern "C" void kernel_launch(void* const* d_in, const int* in_sizes, int n_in,
                              void* d_out, int out_size)
{
    const float* x        = (const float*)d_in[0];
    const int*   delays   = (const int*)  d_in[1];
    const float* w_in     = (const float*)d_in[2];
    const float* w_rec    = (const float*)d_in[3];
    const float* w_out    = (const float*)d_in[4];
    const float* alpha    = (const float*)d_in[5];
    const float* rho      = (const float*)d_in[6];
    const float* beta_a   = (const float*)d_in[7];
    const float* beta_out = (const float*)d_in[8];
    float* out = (float*)d_out;

    static bool attr_set = false;
    if (!attr_set) {
        cudaFuncSetAttribute(fused, cudaFuncAttributeMaxDynamicSharedMemorySize, FUSED_SMEM);
        cudaFuncSetAttribute(build_xd, cudaFuncAttributeMaxDynamicSharedMemorySize, XD_SMEM);
        attr_set = true;
    }

    zero_flags    <<<1, 512>>>();
    prep_w        <<<(HH * CP + 255) / 256, 256>>>(w_in);
    prep_wrec_wout<<<(HH * HH + 255) / 256, 256>>>(w_rec, w_out);
    {
        dim3 grid((CP + XC - 1) / XC, (TT + XT - 1) / XT, BB);  // (6,4,128)
        build_xd<<<grid, 256, XD_SMEM>>>(x, delays);
    }
    fused<<<BB + MM / 128 * (HH / 128) / 1, 256, FUSED_SMEM>>>(  // 128 + 4000
        alpha, rho, beta_a, beta_out, out);
    // note: grid = 128 SNN CTAs + 4000 GEMM CTAs = 4128
}